// round 1
// baseline (speedup 1.0000x reference)
#include <cuda_runtime.h>

// LSTMModel: B=1024, T=256, I=5, H=64, L=3, O=1, fp32.
// Strategy:
//   per layer:  xg = in @ w_ih^T + (b_ih+b_hh)  (bulk parallel GEMM -> g_xg)
//               persistent recurrent kernel: 128 blocks x 8 batch rows,
//               w_hh rows register-resident, h in smem, 256-step loop.
//   final:      out = h_last @ w_fc^T + b_fc
// Scratch via __device__ globals (no allocation anywhere).

#define B_SZ 1024
#define T_SZ 256
#define I_SZ 5
#define H_SZ 64
#define G_SZ 256   // 4*H

__device__ float g_xg[(size_t)B_SZ * T_SZ * G_SZ];  // 268 MB gate-preactivation buffer
__device__ float g_h [(size_t)B_SZ * T_SZ * H_SZ];  // 67 MB layer output / h_last buffer
__device__ float g_wT[H_SZ * G_SZ];                 // transposed w_ih for layers 1/2

__device__ __forceinline__ float sigf(float x) {
    // 1/(1+e^-x); for x << 0, __expf(-x) -> inf, 1/inf -> 0: safe.
    return __fdividef(1.0f, 1.0f + __expf(-x));
}
__device__ __forceinline__ float tanh_fast(float x) {
    // sign-safe: e = exp(-2|x|) <= 1, no overflow/NaN for large |x| (c can drift).
    float ax = fabsf(x);
    float e  = __expf(-2.0f * ax);
    float r  = __fdividef(1.0f - e, 1.0f + e);
    return copysignf(r, x);
}

// ---------------------------------------------------------------------------
// Layer 0 input projection: K=5. Each thread owns one gate column (weights in
// regs), streams 64 rows per block. Memory-bound (268 MB of xg writes).
// ---------------------------------------------------------------------------
__global__ __launch_bounds__(256) void xg_gemm5(
    const float* __restrict__ x, const float* __restrict__ w,
    const float* __restrict__ b_ih, const float* __restrict__ b_hh)
{
    __shared__ float xs[64 * I_SZ];
    const int t    = threadIdx.x;        // gate index 0..255
    const int row0 = blockIdx.x * 64;    // row = b*T + t_step

    float wr[I_SZ];
#pragma unroll
    for (int k = 0; k < I_SZ; k++) wr[k] = w[t * I_SZ + k];
    const float bias = b_ih[t] + b_hh[t];

    for (int v = t; v < 64 * I_SZ; v += 256)
        xs[v] = x[(size_t)row0 * I_SZ + v];
    __syncthreads();

#pragma unroll 4
    for (int r = 0; r < 64; r++) {
        float acc = bias;
#pragma unroll
        for (int k = 0; k < I_SZ; k++) acc = fmaf(xs[r * I_SZ + k], wr[k], acc);
        g_xg[(size_t)(row0 + r) * G_SZ + t] = acc;
    }
}

// ---------------------------------------------------------------------------
// Transpose w_ih [256,64] -> g_wT [64,256] so the GEMM's smem loads coalesce.
// ---------------------------------------------------------------------------
__global__ __launch_bounds__(256) void transpose_w(const float* __restrict__ w)
{
    int idx = blockIdx.x * 256 + threadIdx.x;  // < 64*256
    int g = idx >> 6, k = idx & 63;
    g_wT[k * G_SZ + g] = w[idx];
}

// ---------------------------------------------------------------------------
// Layers 1/2 input projection: [262144,64] @ [64,256] + bias -> g_xg.
// 64x256 block tile, 8x8 register tile per thread (FMA:LDS-float = 4:1),
// two k=32 chunks so static smem stays < 48 KB.
// ---------------------------------------------------------------------------
__global__ __launch_bounds__(256) void xg_gemm64(
    const float* __restrict__ b_ih, const float* __restrict__ b_hh)
{
    __shared__ float in_s[64][32];    // 8 KB
    __shared__ float w_s[32][260];    // 33.3 KB, padded: conflict-light float4 reads
    const int t    = threadIdx.x;
    const int row0 = blockIdx.x * 64;
    const int tcol = t & 31, trow = t >> 5;
    const int g0   = tcol * 8;

    float acc[8][8];
#pragma unroll
    for (int jj = 0; jj < 8; jj++) {
        float bias = b_ih[g0 + jj] + b_hh[g0 + jj];
#pragma unroll
        for (int ii = 0; ii < 8; ii++) acc[ii][jj] = bias;
    }

    for (int kc = 0; kc < 2; kc++) {
        __syncthreads();  // protect smem reuse across chunks
        // input tile: 64 rows x 32 k, coalesced float4
#pragma unroll
        for (int u = 0; u < 2; u++) {
            int v = u * 256 + t;
            int r = v >> 3, kq = v & 7;
            float4 d = *(const float4*)&g_h[(size_t)(row0 + r) * H_SZ + kc * 32 + kq * 4];
            *(float4*)&in_s[r][kq * 4] = d;
        }
        // weight tile from pre-transposed g_wT: coalesced
#pragma unroll
        for (int u = 0; u < 8; u++) {
            int v = u * 256 + t;
            int k = v >> 6, gq = v & 63;
            float4 d = *(const float4*)&g_wT[(kc * 32 + k) * G_SZ + gq * 4];
            *(float4*)&w_s[k][gq * 4] = d;
        }
        __syncthreads();

#pragma unroll 4
        for (int k = 0; k < 32; k++) {
            float a[8];
#pragma unroll
            for (int ii = 0; ii < 8; ii++) a[ii] = in_s[trow * 8 + ii][k];  // broadcast
            float4 bb0 = *(const float4*)&w_s[k][g0];
            float4 bb1 = *(const float4*)&w_s[k][g0 + 4];
            float bcol[8] = {bb0.x, bb0.y, bb0.z, bb0.w, bb1.x, bb1.y, bb1.z, bb1.w};
#pragma unroll
            for (int ii = 0; ii < 8; ii++)
#pragma unroll
                for (int jj = 0; jj < 8; jj++)
                    acc[ii][jj] = fmaf(a[ii], bcol[jj], acc[ii][jj]);
        }
    }

#pragma unroll
    for (int ii = 0; ii < 8; ii++) {
        size_t base = (size_t)(row0 + trow * 8 + ii) * G_SZ + g0;
        float4 o0 = make_float4(acc[ii][0], acc[ii][1], acc[ii][2], acc[ii][3]);
        float4 o1 = make_float4(acc[ii][4], acc[ii][5], acc[ii][6], acc[ii][7]);
        *(float4*)&g_xg[base]     = o0;
        *(float4*)&g_xg[base + 4] = o1;
    }
}

// ---------------------------------------------------------------------------
// Recurrent scan, one layer. Grid = 128 blocks x 8 batch rows, 256 threads.
// Thread g keeps w_hh[g][0..63] in registers for all 256 steps; h broadcasts
// from smem (no bank conflicts). Gates round-trip through smem for the
// elementwise phase; c is register-resident per (row, hidden) pair.
// write_all=1: store full h sequence; write_all=0 (last layer): only t=T-1,
// compact [B,H] layout for the FC.
// ---------------------------------------------------------------------------
__global__ __launch_bounds__(256) void lstm_rec(const float* __restrict__ w_hh,
                                                int write_all)
{
    __shared__ float h_s[8][H_SZ];      // 2 KB
    __shared__ float gates_s[8][G_SZ];  // 8 KB
    const int t  = threadIdx.x;         // gate column
    const int b0 = blockIdx.x * 8;

    // register-resident weights (persistent across all timesteps)
    float w[H_SZ];
#pragma unroll
    for (int q = 0; q < 16; q++) {
        float4 v = *(const float4*)&w_hh[t * H_SZ + q * 4];
        w[q * 4 + 0] = v.x; w[q * 4 + 1] = v.y;
        w[q * 4 + 2] = v.z; w[q * 4 + 3] = v.w;
    }

    ((float*)h_s)[t]       = 0.0f;
    ((float*)h_s)[t + 256] = 0.0f;

    const int j   = t & 63;     // hidden index for epilogue
    const int r0e = t >> 6;     // epilogue rows: r0e (0..3), r0e+4
    const int r1e = r0e + 4;
    float c0 = 0.0f, c1 = 0.0f;

    // prefetch xg for step 0
    float xn[8];
#pragma unroll
    for (int r = 0; r < 8; r++)
        xn[r] = g_xg[((size_t)(b0 + r) * T_SZ) * G_SZ + t];

    __syncthreads();

    for (int step = 0; step < T_SZ; step++) {
        float acc[8];
#pragma unroll
        for (int r = 0; r < 8; r++) acc[r] = xn[r];

        // prefetch next step's xg under the GEMM
        if (step + 1 < T_SZ) {
#pragma unroll
            for (int r = 0; r < 8; r++)
                xn[r] = g_xg[((size_t)(b0 + r) * T_SZ + step + 1) * G_SZ + t];
        }

        // gates[r][t] += sum_k h[r][k] * w_hh[t][k]
        const float4* h4 = (const float4*)&h_s[0][0];
#pragma unroll
        for (int k4 = 0; k4 < 16; k4++) {
            const float wx = w[k4 * 4 + 0], wy = w[k4 * 4 + 1];
            const float wz = w[k4 * 4 + 2], ww = w[k4 * 4 + 3];
#pragma unroll
            for (int r = 0; r < 8; r++) {
                float4 hv = h4[r * 16 + k4];  // warp-broadcast load
                acc[r] = fmaf(hv.x, wx, acc[r]);
                acc[r] = fmaf(hv.y, wy, acc[r]);
                acc[r] = fmaf(hv.z, wz, acc[r]);
                acc[r] = fmaf(hv.w, ww, acc[r]);
            }
        }
#pragma unroll
        for (int r = 0; r < 8; r++) gates_s[r][t] = acc[r];
        __syncthreads();

        // elementwise LSTM cell: this thread owns (r0e,j) and (r1e,j)
        {
            float iv = sigf(gates_s[r0e][j]);
            float fv = sigf(gates_s[r0e][64 + j]);
            float gv = tanh_fast(gates_s[r0e][128 + j]);
            float ov = sigf(gates_s[r0e][192 + j]);
            c0 = fmaf(fv, c0, iv * gv);
            float hv = ov * tanh_fast(c0);
            h_s[r0e][j] = hv;
            if (write_all)
                g_h[((size_t)(b0 + r0e) * T_SZ + step) * H_SZ + j] = hv;
            else if (step == T_SZ - 1)
                g_h[(size_t)(b0 + r0e) * H_SZ + j] = hv;
        }
        {
            float iv = sigf(gates_s[r1e][j]);
            float fv = sigf(gates_s[r1e][64 + j]);
            float gv = tanh_fast(gates_s[r1e][128 + j]);
            float ov = sigf(gates_s[r1e][192 + j]);
            c1 = fmaf(fv, c1, iv * gv);
            float hv = ov * tanh_fast(c1);
            h_s[r1e][j] = hv;
            if (write_all)
                g_h[((size_t)(b0 + r1e) * T_SZ + step) * H_SZ + j] = hv;
            else if (step == T_SZ - 1)
                g_h[(size_t)(b0 + r1e) * H_SZ + j] = hv;
        }
        __syncthreads();  // h_s ready for next step's GEMM
    }
}

// ---------------------------------------------------------------------------
// Final FC: out[b] = h_last[b,:] . w_fc + b_fc   (O=1)
// ---------------------------------------------------------------------------
__global__ __launch_bounds__(256) void fc_kernel(const float* __restrict__ wfc,
                                                 const float* __restrict__ bfc,
                                                 float* __restrict__ out)
{
    int b = blockIdx.x * 256 + threadIdx.x;  // < 1024
    float acc = bfc[0];
#pragma unroll
    for (int q = 0; q < 16; q++) {
        float4 hv = *(const float4*)&g_h[b * H_SZ + q * 4];
        float4 wv = *(const float4*)&wfc[q * 4];
        acc = fmaf(hv.x, wv.x, acc);
        acc = fmaf(hv.y, wv.y, acc);
        acc = fmaf(hv.z, wv.z, acc);
        acc = fmaf(hv.w, wv.w, acc);
    }
    out[b] = acc;
}

// ---------------------------------------------------------------------------
extern "C" void kernel_launch(void* const* d_in, const int* in_sizes, int n_in,
                              void* d_out, int out_size)
{
    (void)in_sizes; (void)n_in; (void)out_size;
    const float* x     = (const float*)d_in[0];
    const float* w_ih0 = (const float*)d_in[1];
    const float* w_hh0 = (const float*)d_in[2];
    const float* b_ih0 = (const float*)d_in[3];
    const float* b_hh0 = (const float*)d_in[4];
    const float* w_ih1 = (const float*)d_in[5];
    const float* w_hh1 = (const float*)d_in[6];
    const float* b_ih1 = (const float*)d_in[7];
    const float* b_hh1 = (const float*)d_in[8];
    const float* w_ih2 = (const float*)d_in[9];
    const float* w_hh2 = (const float*)d_in[10];
    const float* b_ih2 = (const float*)d_in[11];
    const float* b_hh2 = (const float*)d_in[12];
    const float* w_fc  = (const float*)d_in[13];
    const float* b_fc  = (const float*)d_in[14];
    float* out = (float*)d_out;

    const int NROWS = B_SZ * T_SZ;  // 262144

    // layer 0
    xg_gemm5<<<NROWS / 64, 256>>>(x, w_ih0, b_ih0, b_hh0);
    lstm_rec<<<B_SZ / 8, 256>>>(w_hh0, 1);

    // layer 1
    transpose_w<<<64, 256>>>(w_ih1);
    xg_gemm64<<<NROWS / 64, 256>>>(b_ih1, b_hh1);
    lstm_rec<<<B_SZ / 8, 256>>>(w_hh1, 1);

    // layer 2 (only last timestep's h is needed downstream)
    transpose_w<<<64, 256>>>(w_ih2);
    xg_gemm64<<<NROWS / 64, 256>>>(b_ih2, b_hh2);
    lstm_rec<<<B_SZ / 8, 256>>>(w_hh2, 0);

    // final projection
    fc_kernel<<<B_SZ / 256, 256>>>(w_fc, b_fc, out);
}

// round 2
// speedup vs baseline: 1.0161x; 1.0161x over previous
#include <cuda_runtime.h>

// LSTMModel: B=1024, T=256, I=5, H=64, L=3, O=1, fp32.
// R1: packed fp32x2 FMA (fma.rn.f32x2) in both hot kernels; 147x7 row
// partition in lstm_rec to use ~all SMs. Bit-exact fp32 math throughout.

#define B_SZ 1024
#define T_SZ 256
#define I_SZ 5
#define H_SZ 64
#define G_SZ 256   // 4*H
#define RPB  7     // rows per lstm_rec block
#define GRID_REC 147  // 147*7 = 1029 >= 1024

typedef unsigned long long u64;

__device__ float g_xg[(size_t)B_SZ * T_SZ * G_SZ];  // gate preactivations
__device__ float g_h [(size_t)B_SZ * T_SZ * H_SZ];  // layer outputs / h_last
__device__ float g_wT[H_SZ * G_SZ];                 // transposed w_ih (layers 1/2)

__device__ __forceinline__ u64 ffma2(u64 a, u64 b, u64 c) {
    u64 d;
    asm("fma.rn.f32x2 %0, %1, %2, %3;" : "=l"(d) : "l"(a), "l"(b), "l"(c));
    return d;
}
__device__ __forceinline__ u64 pack2(float lo, float hi) {
    u64 d;
    asm("mov.b64 %0, {%1, %2};" : "=l"(d) : "f"(lo), "f"(hi));
    return d;
}
__device__ __forceinline__ float sum2(u64 v) {
    float lo, hi;
    asm("mov.b64 {%0, %1}, %2;" : "=f"(lo), "=f"(hi) : "l"(v));
    return lo + hi;
}

__device__ __forceinline__ float sigf(float x) {
    return __fdividef(1.0f, 1.0f + __expf(-x));
}
__device__ __forceinline__ float tanh_fast(float x) {
    float ax = fabsf(x);
    float e  = __expf(-2.0f * ax);
    float r  = __fdividef(1.0f - e, 1.0f + e);
    return copysignf(r, x);
}

// ---------------------------------------------------------------------------
// Layer 0 input projection: K=5, memory-bound.
// ---------------------------------------------------------------------------
__global__ __launch_bounds__(256) void xg_gemm5(
    const float* __restrict__ x, const float* __restrict__ w,
    const float* __restrict__ b_ih, const float* __restrict__ b_hh)
{
    __shared__ float xs[64 * I_SZ];
    const int t    = threadIdx.x;
    const int row0 = blockIdx.x * 64;

    float wr[I_SZ];
#pragma unroll
    for (int k = 0; k < I_SZ; k++) wr[k] = w[t * I_SZ + k];
    const float bias = b_ih[t] + b_hh[t];

    for (int v = t; v < 64 * I_SZ; v += 256)
        xs[v] = x[(size_t)row0 * I_SZ + v];
    __syncthreads();

#pragma unroll 4
    for (int r = 0; r < 64; r++) {
        float acc = bias;
#pragma unroll
        for (int k = 0; k < I_SZ; k++) acc = fmaf(xs[r * I_SZ + k], wr[k], acc);
        g_xg[(size_t)(row0 + r) * G_SZ + t] = acc;
    }
}

// ---------------------------------------------------------------------------
// Transpose w_ih [256,64] -> g_wT [64,256].
// ---------------------------------------------------------------------------
__global__ __launch_bounds__(256) void transpose_w(const float* __restrict__ w)
{
    int idx = blockIdx.x * 256 + threadIdx.x;
    int g = idx >> 6, k = idx & 63;
    g_wT[k * G_SZ + g] = w[idx];
}

// ---------------------------------------------------------------------------
// Layers 1/2 input projection: [262144,64] @ [64,256] + bias.
// 64x256 tile, 8x8 register tile, FFMA2 packed along the gate dim
// (b-pairs free from w_s float4 reads; a duplicated via mov.b64).
// ---------------------------------------------------------------------------
__global__ __launch_bounds__(256) void xg_gemm64(
    const float* __restrict__ b_ih, const float* __restrict__ b_hh)
{
    __shared__ __align__(16) float in_s[64][32];   // 8 KB
    __shared__ __align__(16) float w_s[32][260];   // 33.3 KB (padded)
    const int t    = threadIdx.x;
    const int row0 = blockIdx.x * 64;
    const int tcol = t & 31, trow = t >> 5;
    const int g0   = tcol * 8;

    u64 acc2[8][4];  // [row][gate-pair]
#pragma unroll
    for (int jp = 0; jp < 4; jp++) {
        float blo = b_ih[g0 + 2 * jp]     + b_hh[g0 + 2 * jp];
        float bhi = b_ih[g0 + 2 * jp + 1] + b_hh[g0 + 2 * jp + 1];
        u64 bp = pack2(blo, bhi);
#pragma unroll
        for (int ii = 0; ii < 8; ii++) acc2[ii][jp] = bp;
    }

    for (int kc = 0; kc < 2; kc++) {
        __syncthreads();
#pragma unroll
        for (int u = 0; u < 2; u++) {
            int v = u * 256 + t;
            int r = v >> 3, kq = v & 7;
            float4 d = *(const float4*)&g_h[(size_t)(row0 + r) * H_SZ + kc * 32 + kq * 4];
            *(float4*)&in_s[r][kq * 4] = d;
        }
#pragma unroll
        for (int u = 0; u < 8; u++) {
            int v = u * 256 + t;
            int k = v >> 6, gq = v & 63;
            float4 d = *(const float4*)&g_wT[(kc * 32 + k) * G_SZ + gq * 4];
            *(float4*)&w_s[k][gq * 4] = d;
        }
        __syncthreads();

#pragma unroll 4
        for (int k = 0; k < 32; k++) {
            u64 adup[8];
#pragma unroll
            for (int ii = 0; ii < 8; ii++) {
                float a = in_s[trow * 8 + ii][k];  // warp broadcast
                adup[ii] = pack2(a, a);
            }
            ulonglong2 bv0 = *(const ulonglong2*)&w_s[k][g0];      // pairs 0,1
            ulonglong2 bv1 = *(const ulonglong2*)&w_s[k][g0 + 4];  // pairs 2,3
            u64 bp[4] = {bv0.x, bv0.y, bv1.x, bv1.y};
#pragma unroll
            for (int ii = 0; ii < 8; ii++)
#pragma unroll
                for (int jp = 0; jp < 4; jp++)
                    acc2[ii][jp] = ffma2(adup[ii], bp[jp], acc2[ii][jp]);
        }
    }

#pragma unroll
    for (int ii = 0; ii < 8; ii++) {
        size_t base = (size_t)(row0 + trow * 8 + ii) * G_SZ + g0;
        ulonglong2 o0, o1;
        o0.x = acc2[ii][0]; o0.y = acc2[ii][1];
        o1.x = acc2[ii][2]; o1.y = acc2[ii][3];
        *(ulonglong2*)&g_xg[base]     = o0;
        *(ulonglong2*)&g_xg[base + 4] = o1;
    }
}

// ---------------------------------------------------------------------------
// Recurrent scan, one layer. 147 blocks x 7 batch rows, 256 threads.
// Thread t keeps w_hh row t as 32 f32x2 pairs in registers; h broadcasts
// from smem as LDS.128 (2 pairs per load). GEMM uses packed FFMA2 along k,
// halves summed once per step.
// ---------------------------------------------------------------------------
__global__ __launch_bounds__(256) void lstm_rec(const float* __restrict__ w_hh,
                                                int write_all)
{
    __shared__ __align__(16) float h_s[RPB][H_SZ];
    __shared__ float gates_s[RPB][G_SZ];
    const int t  = threadIdx.x;          // gate column
    const int b0 = blockIdx.x * RPB;

    // register-resident weight pairs (w_hh row t, 64 floats = 32 pairs)
    u64 w2[32];
    {
        const ulonglong2* wv = (const ulonglong2*)(w_hh + t * H_SZ);
#pragma unroll
        for (int q = 0; q < 16; q++) {
            ulonglong2 v = wv[q];
            w2[2 * q]     = v.x;
            w2[2 * q + 1] = v.y;
        }
    }

    for (int v = t; v < RPB * H_SZ; v += 256) ((float*)h_s)[v] = 0.0f;

    // epilogue cell assignment: cell e -> (row e>>6, hidden e&63); 448 cells
    const int r0e = t >> 6, j0 = t & 63;          // cell t      (always valid)
    const int e1  = t + 256;
    const int r1e = e1 >> 6, j1 = e1 & 63;        // cell t+256  (valid if t<192)
    const bool has1 = (t < 192);
    float c0 = 0.0f, c1 = 0.0f;

    // prefetch xg for step 0 (clamp dummy rows)
    float xn[RPB];
#pragma unroll
    for (int r = 0; r < RPB; r++) {
        int br = b0 + r; if (br > B_SZ - 1) br = B_SZ - 1;
        xn[r] = g_xg[((size_t)br * T_SZ) * G_SZ + t];
    }

    __syncthreads();

    for (int step = 0; step < T_SZ; step++) {
        u64 acc2[RPB];
#pragma unroll
        for (int r = 0; r < RPB; r++) acc2[r] = pack2(xn[r], 0.0f);

        // prefetch next step's xg under the GEMM
        if (step + 1 < T_SZ) {
#pragma unroll
            for (int r = 0; r < RPB; r++) {
                int br = b0 + r; if (br > B_SZ - 1) br = B_SZ - 1;
                xn[r] = g_xg[((size_t)br * T_SZ + step + 1) * G_SZ + t];
            }
        }

        // gates[r][t] += sum_k h[r][k] * w_hh[t][k]   (packed pairs along k)
        const ulonglong2* h2 = (const ulonglong2*)&h_s[0][0];
#pragma unroll
        for (int q = 0; q < 16; q++) {
            const u64 wa = w2[2 * q], wb = w2[2 * q + 1];
#pragma unroll
            for (int r = 0; r < RPB; r++) {
                ulonglong2 hv = h2[r * 16 + q];   // LDS.128 broadcast
                acc2[r] = ffma2(hv.x, wa, acc2[r]);
                acc2[r] = ffma2(hv.y, wb, acc2[r]);
            }
        }
#pragma unroll
        for (int r = 0; r < RPB; r++) gates_s[r][t] = sum2(acc2[r]);
        __syncthreads();

        // elementwise LSTM cell
        {
            float iv = sigf(gates_s[r0e][j0]);
            float fv = sigf(gates_s[r0e][64 + j0]);
            float gv = tanh_fast(gates_s[r0e][128 + j0]);
            float ov = sigf(gates_s[r0e][192 + j0]);
            c0 = fmaf(fv, c0, iv * gv);
            float hv = ov * tanh_fast(c0);
            h_s[r0e][j0] = hv;
            int br = b0 + r0e;
            if (br < B_SZ) {
                if (write_all)
                    g_h[((size_t)br * T_SZ + step) * H_SZ + j0] = hv;
                else if (step == T_SZ - 1)
                    g_h[(size_t)br * H_SZ + j0] = hv;
            }
        }
        if (has1) {
            float iv = sigf(gates_s[r1e][j1]);
            float fv = sigf(gates_s[r1e][64 + j1]);
            float gv = tanh_fast(gates_s[r1e][128 + j1]);
            float ov = sigf(gates_s[r1e][192 + j1]);
            c1 = fmaf(fv, c1, iv * gv);
            float hv = ov * tanh_fast(c1);
            h_s[r1e][j1] = hv;
            int br = b0 + r1e;
            if (br < B_SZ) {
                if (write_all)
                    g_h[((size_t)br * T_SZ + step) * H_SZ + j1] = hv;
                else if (step == T_SZ - 1)
                    g_h[(size_t)br * H_SZ + j1] = hv;
            }
        }
        __syncthreads();
    }
}

// ---------------------------------------------------------------------------
// Final FC: out[b] = h_last[b,:] . w_fc + b_fc   (O=1)
// ---------------------------------------------------------------------------
__global__ __launch_bounds__(256) void fc_kernel(const float* __restrict__ wfc,
                                                 const float* __restrict__ bfc,
                                                 float* __restrict__ out)
{
    int b = blockIdx.x * 256 + threadIdx.x;
    float acc = bfc[0];
#pragma unroll
    for (int q = 0; q < 16; q++) {
        float4 hv = *(const float4*)&g_h[b * H_SZ + q * 4];
        float4 wv = *(const float4*)&wfc[q * 4];
        acc = fmaf(hv.x, wv.x, acc);
        acc = fmaf(hv.y, wv.y, acc);
        acc = fmaf(hv.z, wv.z, acc);
        acc = fmaf(hv.w, wv.w, acc);
    }
    out[b] = acc;
}

// ---------------------------------------------------------------------------
extern "C" void kernel_launch(void* const* d_in, const int* in_sizes, int n_in,
                              void* d_out, int out_size)
{
    (void)in_sizes; (void)n_in; (void)out_size;
    const float* x     = (const float*)d_in[0];
    const float* w_ih0 = (const float*)d_in[1];
    const float* w_hh0 = (const float*)d_in[2];
    const float* b_ih0 = (const float*)d_in[3];
    const float* b_hh0 = (const float*)d_in[4];
    const float* w_ih1 = (const float*)d_in[5];
    const float* w_hh1 = (const float*)d_in[6];
    const float* b_ih1 = (const float*)d_in[7];
    const float* b_hh1 = (const float*)d_in[8];
    const float* w_ih2 = (const float*)d_in[9];
    const float* w_hh2 = (const float*)d_in[10];
    const float* b_ih2 = (const float*)d_in[11];
    const float* b_hh2 = (const float*)d_in[12];
    const float* w_fc  = (const float*)d_in[13];
    const float* b_fc  = (const float*)d_in[14];
    float* out = (float*)d_out;

    const int NROWS = B_SZ * T_SZ;  // 262144

    // layer 0
    xg_gemm5<<<NROWS / 64, 256>>>(x, w_ih0, b_ih0, b_hh0);
    lstm_rec<<<GRID_REC, 256>>>(w_hh0, 1);

    // layer 1
    transpose_w<<<64, 256>>>(w_ih1);
    xg_gemm64<<<NROWS / 64, 256>>>(b_ih1, b_hh1);
    lstm_rec<<<GRID_REC, 256>>>(w_hh1, 1);

    // layer 2 (only last timestep's h is needed downstream)
    transpose_w<<<64, 256>>>(w_ih2);
    xg_gemm64<<<NROWS / 64, 256>>>(b_ih2, b_hh2);
    lstm_rec<<<GRID_REC, 256>>>(w_hh2, 0);

    // final projection
    fc_kernel<<<B_SZ / 256, 256>>>(w_fc, b_fc, out);
}

// round 3
// speedup vs baseline: 1.1897x; 1.1709x over previous
#include <cuda_runtime.h>

// LSTMModel: B=1024, T=256, I=5, H=64, L=3, O=1, fp32.
// R2: occupancy-driven. lstm_rec: 256 blocks x 4 rows (all resident, 2/SM on
// long-pole SMs -> two independent chains hide phase latency), 1 cell/thread
// epilogue. xg_gemm64: __launch_bounds__(256,2) to restore 2 CTAs/SM.

#define B_SZ 1024
#define T_SZ 256
#define I_SZ 5
#define H_SZ 64
#define G_SZ 256   // 4*H
#define RPB  4     // rows per lstm_rec block
#define GRID_REC (B_SZ / RPB)   // 256

typedef unsigned long long u64;

__device__ float g_xg[(size_t)B_SZ * T_SZ * G_SZ];  // gate preactivations
__device__ float g_h [(size_t)B_SZ * T_SZ * H_SZ];  // layer outputs / h_last
__device__ float g_wT[H_SZ * G_SZ];                 // transposed w_ih (layers 1/2)

__device__ __forceinline__ u64 ffma2(u64 a, u64 b, u64 c) {
    u64 d;
    asm("fma.rn.f32x2 %0, %1, %2, %3;" : "=l"(d) : "l"(a), "l"(b), "l"(c));
    return d;
}
__device__ __forceinline__ u64 pack2(float lo, float hi) {
    u64 d;
    asm("mov.b64 %0, {%1, %2};" : "=l"(d) : "f"(lo), "f"(hi));
    return d;
}
__device__ __forceinline__ float sum2(u64 v) {
    float lo, hi;
    asm("mov.b64 {%0, %1}, %2;" : "=f"(lo), "=f"(hi) : "l"(v));
    return lo + hi;
}

__device__ __forceinline__ float sigf(float x) {
    return __fdividef(1.0f, 1.0f + __expf(-x));
}
__device__ __forceinline__ float tanh_fast(float x) {
    float ax = fabsf(x);
    float e  = __expf(-2.0f * ax);
    float r  = __fdividef(1.0f - e, 1.0f + e);
    return copysignf(r, x);
}

// ---------------------------------------------------------------------------
// Layer 0 input projection: K=5, memory-bound.
// ---------------------------------------------------------------------------
__global__ __launch_bounds__(256) void xg_gemm5(
    const float* __restrict__ x, const float* __restrict__ w,
    const float* __restrict__ b_ih, const float* __restrict__ b_hh)
{
    __shared__ float xs[64 * I_SZ];
    const int t    = threadIdx.x;
    const int row0 = blockIdx.x * 64;

    float wr[I_SZ];
#pragma unroll
    for (int k = 0; k < I_SZ; k++) wr[k] = w[t * I_SZ + k];
    const float bias = b_ih[t] + b_hh[t];

    for (int v = t; v < 64 * I_SZ; v += 256)
        xs[v] = x[(size_t)row0 * I_SZ + v];
    __syncthreads();

#pragma unroll 4
    for (int r = 0; r < 64; r++) {
        float acc = bias;
#pragma unroll
        for (int k = 0; k < I_SZ; k++) acc = fmaf(xs[r * I_SZ + k], wr[k], acc);
        g_xg[(size_t)(row0 + r) * G_SZ + t] = acc;
    }
}

// ---------------------------------------------------------------------------
// Transpose w_ih [256,64] -> g_wT [64,256].
// ---------------------------------------------------------------------------
__global__ __launch_bounds__(256) void transpose_w(const float* __restrict__ w)
{
    int idx = blockIdx.x * 256 + threadIdx.x;
    int g = idx >> 6, k = idx & 63;
    g_wT[k * G_SZ + g] = w[idx];
}

// ---------------------------------------------------------------------------
// Layers 1/2 input projection: [262144,64] @ [64,256] + bias.
// 64x256 tile, 8x8 register tile, FFMA2 packed along the gate dim.
// __launch_bounds__(256,2): cap regs at 128 so 2 CTAs stay resident.
// ---------------------------------------------------------------------------
__global__ __launch_bounds__(256, 2) void xg_gemm64(
    const float* __restrict__ b_ih, const float* __restrict__ b_hh)
{
    __shared__ __align__(16) float in_s[64][32];   // 8 KB
    __shared__ __align__(16) float w_s[32][260];   // 33.3 KB (padded)
    const int t    = threadIdx.x;
    const int row0 = blockIdx.x * 64;
    const int tcol = t & 31, trow = t >> 5;
    const int g0   = tcol * 8;

    u64 acc2[8][4];  // [row][gate-pair]
#pragma unroll
    for (int jp = 0; jp < 4; jp++) {
        float blo = b_ih[g0 + 2 * jp]     + b_hh[g0 + 2 * jp];
        float bhi = b_ih[g0 + 2 * jp + 1] + b_hh[g0 + 2 * jp + 1];
        u64 bp = pack2(blo, bhi);
#pragma unroll
        for (int ii = 0; ii < 8; ii++) acc2[ii][jp] = bp;
    }

    for (int kc = 0; kc < 2; kc++) {
        __syncthreads();
#pragma unroll
        for (int u = 0; u < 2; u++) {
            int v = u * 256 + t;
            int r = v >> 3, kq = v & 7;
            float4 d = *(const float4*)&g_h[(size_t)(row0 + r) * H_SZ + kc * 32 + kq * 4];
            *(float4*)&in_s[r][kq * 4] = d;
        }
#pragma unroll
        for (int u = 0; u < 8; u++) {
            int v = u * 256 + t;
            int k = v >> 6, gq = v & 63;
            float4 d = *(const float4*)&g_wT[(kc * 32 + k) * G_SZ + gq * 4];
            *(float4*)&w_s[k][gq * 4] = d;
        }
        __syncthreads();

#pragma unroll 4
        for (int k = 0; k < 32; k++) {
            u64 adup[8];
#pragma unroll
            for (int ii = 0; ii < 8; ii++) {
                float a = in_s[trow * 8 + ii][k];  // warp broadcast
                adup[ii] = pack2(a, a);
            }
            ulonglong2 bv0 = *(const ulonglong2*)&w_s[k][g0];      // pairs 0,1
            ulonglong2 bv1 = *(const ulonglong2*)&w_s[k][g0 + 4];  // pairs 2,3
            u64 bp[4] = {bv0.x, bv0.y, bv1.x, bv1.y};
#pragma unroll
            for (int ii = 0; ii < 8; ii++)
#pragma unroll
                for (int jp = 0; jp < 4; jp++)
                    acc2[ii][jp] = ffma2(adup[ii], bp[jp], acc2[ii][jp]);
        }
    }

#pragma unroll
    for (int ii = 0; ii < 8; ii++) {
        size_t base = (size_t)(row0 + trow * 8 + ii) * G_SZ + g0;
        ulonglong2 o0, o1;
        o0.x = acc2[ii][0]; o0.y = acc2[ii][1];
        o1.x = acc2[ii][2]; o1.y = acc2[ii][3];
        *(ulonglong2*)&g_xg[base]     = o0;
        *(ulonglong2*)&g_xg[base + 4] = o1;
    }
}

// ---------------------------------------------------------------------------
// Recurrent scan, one layer. 256 blocks x 4 batch rows, 256 threads,
// __launch_bounds__(256,2) so all 256 blocks are co-resident (2/SM on 104
// SMs): two independent recurrent chains per SM hide phase latency.
// Thread t: GEMM phase computes gate column t for 4 rows (w_hh row t in regs
// as f32x2 pairs); epilogue phase owns exactly one cell (row t>>6, j t&63).
// ---------------------------------------------------------------------------
__global__ __launch_bounds__(256, 2) void lstm_rec(const float* __restrict__ w_hh,
                                                   int write_all)
{
    __shared__ __align__(16) float h_s[RPB][H_SZ];      // 1 KB
    __shared__ float gates_s[RPB][G_SZ];                // 4 KB
    const int t  = threadIdx.x;          // gate column
    const int b0 = blockIdx.x * RPB;

    // register-resident weight pairs (w_hh row t, 64 floats = 32 pairs)
    u64 w2[32];
    {
        const ulonglong2* wv = (const ulonglong2*)(w_hh + t * H_SZ);
#pragma unroll
        for (int q = 0; q < 16; q++) {
            ulonglong2 v = wv[q];
            w2[2 * q]     = v.x;
            w2[2 * q + 1] = v.y;
        }
    }

    for (int v = t; v < RPB * H_SZ; v += 256) ((float*)h_s)[v] = 0.0f;

    // epilogue: one cell per thread
    const int re = t >> 6, je = t & 63;
    float c = 0.0f;

    // prefetch xg for step 0
    float xn[RPB];
#pragma unroll
    for (int r = 0; r < RPB; r++)
        xn[r] = g_xg[((size_t)(b0 + r) * T_SZ) * G_SZ + t];

    __syncthreads();

    for (int step = 0; step < T_SZ; step++) {
        u64 acc2[RPB];
#pragma unroll
        for (int r = 0; r < RPB; r++) acc2[r] = pack2(xn[r], 0.0f);

        // prefetch next step's xg under the GEMM
        if (step + 1 < T_SZ) {
#pragma unroll
            for (int r = 0; r < RPB; r++)
                xn[r] = g_xg[((size_t)(b0 + r) * T_SZ + step + 1) * G_SZ + t];
        }

        // gates[r][t] += sum_k h[r][k] * w_hh[t][k]   (packed pairs along k)
        const ulonglong2* h2 = (const ulonglong2*)&h_s[0][0];
#pragma unroll
        for (int q = 0; q < 16; q++) {
            const u64 wa = w2[2 * q], wb = w2[2 * q + 1];
#pragma unroll
            for (int r = 0; r < RPB; r++) {
                ulonglong2 hv = h2[r * 16 + q];   // LDS.128 block broadcast
                acc2[r] = ffma2(hv.x, wa, acc2[r]);
                acc2[r] = ffma2(hv.y, wb, acc2[r]);
            }
        }
#pragma unroll
        for (int r = 0; r < RPB; r++) gates_s[r][t] = sum2(acc2[r]);
        __syncthreads();

        // elementwise LSTM cell: one cell per thread
        {
            float iv = sigf(gates_s[re][je]);
            float fv = sigf(gates_s[re][64 + je]);
            float gv = tanh_fast(gates_s[re][128 + je]);
            float ov = sigf(gates_s[re][192 + je]);
            c = fmaf(fv, c, iv * gv);
            float hv = ov * tanh_fast(c);
            h_s[re][je] = hv;
            if (write_all)
                g_h[((size_t)(b0 + re) * T_SZ + step) * H_SZ + je] = hv;
            else if (step == T_SZ - 1)
                g_h[(size_t)(b0 + re) * H_SZ + je] = hv;
        }
        __syncthreads();
    }
}

// ---------------------------------------------------------------------------
// Final FC: out[b] = h_last[b,:] . w_fc + b_fc   (O=1)
// ---------------------------------------------------------------------------
__global__ __launch_bounds__(256) void fc_kernel(const float* __restrict__ wfc,
                                                 const float* __restrict__ bfc,
                                                 float* __restrict__ out)
{
    int b = blockIdx.x * 256 + threadIdx.x;
    float acc = bfc[0];
#pragma unroll
    for (int q = 0; q < 16; q++) {
        float4 hv = *(const float4*)&g_h[b * H_SZ + q * 4];
        float4 wv = *(const float4*)&wfc[q * 4];
        acc = fmaf(hv.x, wv.x, acc);
        acc = fmaf(hv.y, wv.y, acc);
        acc = fmaf(hv.z, wv.z, acc);
        acc = fmaf(hv.w, wv.w, acc);
    }
    out[b] = acc;
}

// ---------------------------------------------------------------------------
extern "C" void kernel_launch(void* const* d_in, const int* in_sizes, int n_in,
                              void* d_out, int out_size)
{
    (void)in_sizes; (void)n_in; (void)out_size;
    const float* x     = (const float*)d_in[0];
    const float* w_ih0 = (const float*)d_in[1];
    const float* w_hh0 = (const float*)d_in[2];
    const float* b_ih0 = (const float*)d_in[3];
    const float* b_hh0 = (const float*)d_in[4];
    const float* w_ih1 = (const float*)d_in[5];
    const float* w_hh1 = (const float*)d_in[6];
    const float* b_ih1 = (const float*)d_in[7];
    const float* b_hh1 = (const float*)d_in[8];
    const float* w_ih2 = (const float*)d_in[9];
    const float* w_hh2 = (const float*)d_in[10];
    const float* b_ih2 = (const float*)d_in[11];
    const float* b_hh2 = (const float*)d_in[12];
    const float* w_fc  = (const float*)d_in[13];
    const float* b_fc  = (const float*)d_in[14];
    float* out = (float*)d_out;

    const int NROWS = B_SZ * T_SZ;  // 262144

    // layer 0
    xg_gemm5<<<NROWS / 64, 256>>>(x, w_ih0, b_ih0, b_hh0);
    lstm_rec<<<GRID_REC, 256>>>(w_hh0, 1);

    // layer 1
    transpose_w<<<64, 256>>>(w_ih1);
    xg_gemm64<<<NROWS / 64, 256>>>(b_ih1, b_hh1);
    lstm_rec<<<GRID_REC, 256>>>(w_hh1, 1);

    // layer 2 (only last timestep's h is needed downstream)
    transpose_w<<<64, 256>>>(w_ih2);
    xg_gemm64<<<NROWS / 64, 256>>>(b_ih2, b_hh2);
    lstm_rec<<<GRID_REC, 256>>>(w_hh2, 0);

    // final projection
    fc_kernel<<<B_SZ / 256, 256>>>(w_fc, b_fc, out);
}